// round 4
// baseline (speedup 1.0000x reference)
#include <cuda_runtime.h>
#include <math.h>

// Problem constants
#define B_   8
#define C_   256
#define N_   4096
#define D_   32
#define TQ   64
#define TK   64
#define OCH  320   // 32 (wq) + 32 (wk) + 256 (wv)

// ---------------- scratch (device globals; no cudaMalloc allowed) ----------
__device__ __align__(16) float g_W[OCH * C_];         // concat weights [320][256]
__device__ __align__(16) float g_bias[OCH];           // concat bias
__device__ __align__(16) float g_P[(size_t)B_ * OCH * N_];  // projections [b][320][4096] ~40MB

// ---------------- fp32x2 packed-math helpers (sm_100+ PTX) -----------------
__device__ __forceinline__ unsigned long long pk2(float lo, float hi) {
    unsigned long long r;
    asm("mov.b64 %0, {%1, %2};" : "=l"(r)
        : "r"(__float_as_uint(lo)), "r"(__float_as_uint(hi)));
    return r;
}
__device__ __forceinline__ void upk2(unsigned long long v, float& lo, float& hi) {
    unsigned int a, b;
    asm("mov.b64 {%0, %1}, %2;" : "=r"(a), "=r"(b) : "l"(v));
    lo = __uint_as_float(a); hi = __uint_as_float(b);
}
__device__ __forceinline__ void fma2(unsigned long long& d,
                                     unsigned long long a, unsigned long long b) {
    asm("fma.rn.f32x2 %0, %1, %2, %0;" : "+l"(d) : "l"(a), "l"(b));
}
__device__ __forceinline__ void mul2(unsigned long long& d, unsigned long long a) {
    asm("mul.rn.f32x2 %0, %0, %1;" : "+l"(d) : "l"(a));
}

// ---------------- kernel 0: concatenate wq/wk/wv + biases ------------------
__global__ void concat_kernel(const float* __restrict__ wq, const float* __restrict__ bq,
                              const float* __restrict__ wk, const float* __restrict__ bk,
                              const float* __restrict__ wv, const float* __restrict__ bv) {
    int idx = blockIdx.x * 256 + threadIdx.x;
    if (idx < 32 * C_)            g_W[idx] = wq[idx];
    else if (idx < 64 * C_)       g_W[idx] = wk[idx - 32 * C_];
    else if (idx < OCH * C_)      g_W[idx] = wv[idx - 64 * C_];
    int j = idx - OCH * C_;
    if (j >= 0 && j < OCH) {
        g_bias[j] = (j < 32) ? bq[j] : (j < 64) ? bk[j - 32] : bv[j - 64];
    }
}

// ---------------- kernel 1: projection GEMM P = W @ x + b ------------------
// grid: (N/64 token tiles, B, 320/64 out tiles), 256 threads.
// Each thread computes a 4(out) x 4(token) register tile via fp32x2 FMA.
__global__ void __launch_bounds__(256)
proj_kernel(const float* __restrict__ x) {
    __shared__ __align__(16) float ws[32 * 68];  // [cc][o], padded
    __shared__ __align__(16) float xs[32 * 68];  // [cc][t], padded

    const int tid = threadIdx.x;
    const int n0  = blockIdx.x * 64;
    const int bb  = blockIdx.y;
    const int o0  = blockIdx.z * 64;
    const int tg  = tid & 15;       // token group (16)
    const int og  = tid >> 4;       // out-ch group (16)

    const float* xb = x + (size_t)bb * C_ * N_;

    unsigned long long acc[4][2];   // [uo][token-pair]
    #pragma unroll
    for (int i = 0; i < 4; i++) { acc[i][0] = 0ull; acc[i][1] = 0ull; }

    for (int cb = 0; cb < C_; cb += 32) {
        #pragma unroll
        for (int r = 0; r < 8; r++) {           // 64 o x 32 cc weights
            int idx = tid + r * 256;
            int ol = idx >> 5, cc = idx & 31;
            ws[cc * 68 + ol] = g_W[(o0 + ol) * C_ + cb + cc];
        }
        #pragma unroll
        for (int r = 0; r < 8; r++) {           // 32 cc x 64 t activations
            int idx = tid + r * 256;
            int cc = idx >> 6, t = idx & 63;
            xs[cc * 68 + t] = xb[(size_t)(cb + cc) * N_ + n0 + t];
        }
        __syncthreads();

        #pragma unroll 8
        for (int cc = 0; cc < 32; cc++) {
            float4 w4 = *(const float4*)&ws[cc * 68 + og * 4];
            float4 x4 = *(const float4*)&xs[cc * 68 + tg * 4];
            unsigned long long xa = pk2(x4.x, x4.y);
            unsigned long long xc = pk2(x4.z, x4.w);
            unsigned long long w0 = pk2(w4.x, w4.x);
            unsigned long long w1 = pk2(w4.y, w4.y);
            unsigned long long w2 = pk2(w4.z, w4.z);
            unsigned long long w3 = pk2(w4.w, w4.w);
            fma2(acc[0][0], xa, w0); fma2(acc[0][1], xc, w0);
            fma2(acc[1][0], xa, w1); fma2(acc[1][1], xc, w1);
            fma2(acc[2][0], xa, w2); fma2(acc[2][1], xc, w2);
            fma2(acc[3][0], xa, w3); fma2(acc[3][1], xc, w3);
        }
        __syncthreads();
    }

    float* P = g_P + ((size_t)bb * OCH + o0) * N_ + n0;
    #pragma unroll
    for (int uo = 0; uo < 4; uo++) {
        int o = og * 4 + uo;
        float bias = g_bias[o0 + o];
        float v0, v1, v2, v3;
        upk2(acc[uo][0], v0, v1);
        upk2(acc[uo][1], v2, v3);
        float4 ov = make_float4(v0 + bias, v1 + bias, v2 + bias, v3 + bias);
        *(float4*)&P[(size_t)o * N_ + tg * 4] = ov;
    }
}

// ---------------- kernel 2: flash attention + residual ---------------------
// Queries = g columns (index j), keys = f columns (index i), values = hh columns.
// Softmax over i. grid (N/TQ, B), 256 threads.
// Thread layout for PV: qgrp = tid>>5 (8 groups of 8 q rows), cgrp = tid&31
// (c = cgrp + 32u, u<8). 8x8 fp32x2 accumulator per thread.
#define FLASH_SMEM_FLOATS 25088   // gs 2048 + fs 2048 + hs 16448 + ps 4352 + 192
#define FLASH_SMEM_BYTES  (FLASH_SMEM_FLOATS * 4)

__global__ void __launch_bounds__(256, 2)
flash_kernel(const float* __restrict__ x, const float* __restrict__ gamma,
             float* __restrict__ out) {
    extern __shared__ __align__(16) float sm[];
    float* gs   = sm;                  // [32][64]   queries (d-major)
    float* fs   = gs + 2048;           // [32][64]   keys
    float* hs   = fs + 2048;           // [64][257]  values (i-major, padded)
    float* ps   = hs + 16448;          // [64][68]   scores/probs (i-major, padded)
    float* m_sh = ps + 4352;           // [64]
    float* l_sh = m_sh + 64;           // [64]
    float* sc_sh = l_sh + 64;          // [64]

    const int tid = threadIdx.x;
    const int bb  = blockIdx.y;
    const int j0  = blockIdx.x * TQ;

    const float* Pb   = g_P + (size_t)bb * OCH * N_;
    const float* fptr = Pb;            // rows 0..31
    const float* gptr = Pb + 32 * N_;  // rows 32..63
    const float* hptr = Pb + 64 * N_;  // rows 64..319

    // load query tile gs[d][q]
    #pragma unroll
    for (int r = 0; r < 2; r++) {
        int idx = tid + r * 256;           // 0..511 float4s
        int d = idx >> 4, q4 = idx & 15;
        *(float4*)&gs[d * 64 + q4 * 4] =
            *(const float4*)&gptr[(size_t)d * N_ + j0 + q4 * 4];
    }
    if (tid < 64) { m_sh[tid] = -INFINITY; l_sh[tid] = 0.0f; }

    const int qgrp = tid >> 5;
    const int cgrp = tid & 31;
    const int tqg  = tid & 15;
    const int tkg  = tid >> 4;

    unsigned long long o2[4][8];       // rows (qgrp*8 + 2r2, +1), cols cgrp+32u
    #pragma unroll
    for (int a = 0; a < 4; a++)
        #pragma unroll
        for (int u = 0; u < 8; u++) o2[a][u] = 0ull;

    for (int k0 = 0; k0 < N_; k0 += TK) {
        __syncthreads();  // prev PV done (and first-iter gs/m/l visible)

        // load key tile fs[d][i]
        #pragma unroll
        for (int r = 0; r < 2; r++) {
            int idx = tid + r * 256;
            int d = idx >> 4, i4 = idx & 15;
            *(float4*)&fs[d * 64 + i4 * 4] =
                *(const float4*)&fptr[(size_t)d * N_ + k0 + i4 * 4];
        }
        // load value tile hs[i][c] (transpose on the fly, pad 257)
        #pragma unroll
        for (int r = 0; r < 16; r++) {
            int idx = tid + r * 256;       // 0..4095 float4s
            int c = idx >> 4, i4 = idx & 15;
            float4 v = *(const float4*)&hptr[(size_t)c * N_ + k0 + i4 * 4];
            hs[(i4 * 4 + 0) * 257 + c] = v.x;
            hs[(i4 * 4 + 1) * 257 + c] = v.y;
            hs[(i4 * 4 + 2) * 257 + c] = v.z;
            hs[(i4 * 4 + 3) * 257 + c] = v.w;
        }
        __syncthreads();

        // ---- QK: s[i][q] = sum_d f[d][i] * g[d][q] --------------------------
        unsigned long long s2[2][4];
        #pragma unroll
        for (int a = 0; a < 2; a++)
            #pragma unroll
            for (int v = 0; v < 4; v++) s2[a][v] = 0ull;

        #pragma unroll 8
        for (int d = 0; d < D_; d++) {
            float4 gq = *(const float4*)&gs[d * 64 + tqg * 4];
            float4 fk = *(const float4*)&fs[d * 64 + tkg * 4];
            unsigned long long ga = pk2(gq.x, gq.y);
            unsigned long long gb = pk2(gq.z, gq.w);
            unsigned long long f0 = pk2(fk.x, fk.x);
            unsigned long long f1 = pk2(fk.y, fk.y);
            unsigned long long f2 = pk2(fk.z, fk.z);
            unsigned long long f3 = pk2(fk.w, fk.w);
            fma2(s2[0][0], ga, f0); fma2(s2[1][0], gb, f0);
            fma2(s2[0][1], ga, f1); fma2(s2[1][1], gb, f1);
            fma2(s2[0][2], ga, f2); fma2(s2[1][2], gb, f2);
            fma2(s2[0][3], ga, f3); fma2(s2[1][3], gb, f3);
        }
        #pragma unroll
        for (int v = 0; v < 4; v++) {
            float a0, a1, a2, a3;
            upk2(s2[0][v], a0, a1);
            upk2(s2[1][v], a2, a3);
            int k = tkg * 4 + v, qb = tqg * 4;
            ps[k * 68 + qb + 0] = a0;
            ps[k * 68 + qb + 1] = a1;
            ps[k * 68 + qb + 2] = a2;
            ps[k * 68 + qb + 3] = a3;
        }
        __syncthreads();

        // ---- online softmax over i (one thread per query) -------------------
        if (tid < 64) {
            int q = tid;
            float mo = m_sh[q], mt = mo;
            #pragma unroll 8
            for (int i = 0; i < TK; i++) mt = fmaxf(mt, ps[i * 68 + q]);
            float sc = __expf(mo - mt);          // 0 on first tile (mo = -inf)
            float ls = 0.0f;
            #pragma unroll 8
            for (int i = 0; i < TK; i++) {
                float e = __expf(ps[i * 68 + q] - mt);
                ps[i * 68 + q] = e;
                ls += e;
            }
            l_sh[q] = l_sh[q] * sc + ls;
            m_sh[q] = mt;
            sc_sh[q] = sc;
        }
        __syncthreads();

        // ---- rescale accumulators ------------------------------------------
        {
            unsigned long long scp[4];
            #pragma unroll
            for (int r2 = 0; r2 < 4; r2++)
                scp[r2] = pk2(sc_sh[qgrp * 8 + 2 * r2], sc_sh[qgrp * 8 + 2 * r2 + 1]);
            #pragma unroll
            for (int r2 = 0; r2 < 4; r2++)
                #pragma unroll
                for (int u = 0; u < 8; u++) mul2(o2[r2][u], scp[r2]);
        }

        // ---- PV: o[q][c] += p[i][q] * h[i][c] --------------------------------
        #pragma unroll 2
        for (int i = 0; i < TK; i++) {
            const float* pr = &ps[i * 68 + qgrp * 8];
            float4 p0 = *(const float4*)pr;
            float4 p1 = *(const float4*)(pr + 4);
            unsigned long long pv0 = pk2(p0.x, p0.y);
            unsigned long long pv1 = pk2(p0.z, p0.w);
            unsigned long long pv2 = pk2(p1.x, p1.y);
            unsigned long long pv3 = pk2(p1.z, p1.w);
            const float* hr = &hs[i * 257 + cgrp];
            #pragma unroll
            for (int u = 0; u < 8; u++) {
                float hv = hr[32 * u];
                unsigned long long h2 = pk2(hv, hv);
                fma2(o2[0][u], pv0, h2);
                fma2(o2[1][u], pv1, h2);
                fma2(o2[2][u], pv2, h2);
                fma2(o2[3][u], pv3, h2);
            }
        }
    }
    __syncthreads();   // all PV reads of hs done before reuse as staging

    // ---- epilogue: out[c][j] = gamma * o/l + x, transposed through smem ----
    const float g0 = gamma[0];
    float linv[8];
    #pragma unroll
    for (int r = 0; r < 8; r++) linv[r] = g0 / l_sh[qgrp * 8 + r];

    #pragma unroll
    for (int r2 = 0; r2 < 4; r2++) {
        #pragma unroll
        for (int u = 0; u < 8; u++) {
            float lo, hi;
            upk2(o2[r2][u], lo, hi);
            int c = cgrp + 32 * u;
            hs[(qgrp * 8 + 2 * r2 + 0) * 257 + c] = lo * linv[2 * r2 + 0];
            hs[(qgrp * 8 + 2 * r2 + 1) * 257 + c] = hi * linv[2 * r2 + 1];
        }
    }
    __syncthreads();

    const float* xb = x   + (size_t)bb * C_ * N_;
    float*       ob = out + (size_t)bb * C_ * N_;
    #pragma unroll
    for (int r = 0; r < 16; r++) {
        int idx = tid + r * 256;           // 0..4095 float4s
        int c = idx >> 4, j4 = idx & 15;
        float4 xv = *(const float4*)&xb[(size_t)c * N_ + j0 + j4 * 4];
        float4 ov;
        ov.x = hs[(j4 * 4 + 0) * 257 + c] + xv.x;
        ov.y = hs[(j4 * 4 + 1) * 257 + c] + xv.y;
        ov.z = hs[(j4 * 4 + 2) * 257 + c] + xv.z;
        ov.w = hs[(j4 * 4 + 3) * 257 + c] + xv.w;
        *(float4*)&ob[(size_t)c * N_ + j0 + j4 * 4] = ov;
    }
}

// ---------------- launch ----------------------------------------------------
extern "C" void kernel_launch(void* const* d_in, const int* in_sizes, int n_in,
                              void* d_out, int out_size) {
    (void)in_sizes; (void)n_in; (void)out_size;
    const float* x     = (const float*)d_in[0];
    const float* wq    = (const float*)d_in[1];
    const float* bq    = (const float*)d_in[2];
    const float* wk    = (const float*)d_in[3];
    const float* bk    = (const float*)d_in[4];
    const float* wv    = (const float*)d_in[5];
    const float* bv    = (const float*)d_in[6];
    const float* gamma = (const float*)d_in[7];
    float* out = (float*)d_out;

    cudaFuncSetAttribute(flash_kernel,
                         cudaFuncAttributeMaxDynamicSharedMemorySize,
                         FLASH_SMEM_BYTES);

    concat_kernel<<<322, 256>>>(wq, bq, wk, bk, wv, bv);
    proj_kernel<<<dim3(N_ / 64, B_, OCH / 64), 256>>>(x);
    flash_kernel<<<dim3(N_ / TQ, B_), 256, FLASH_SMEM_BYTES>>>(x, gamma, out);
}

// round 5
// speedup vs baseline: 1.0013x; 1.0013x over previous
#include <cuda_runtime.h>
#include <math.h>

// Problem constants
#define B_   8
#define C_   256
#define N_   4096
#define D_   32
#define TQ   64
#define TK   64
#define OCH  320   // 32 (wq) + 32 (wk) + 256 (wv)

// ---------------- scratch (device globals; no cudaMalloc allowed) ----------
__device__ __align__(16) float g_W[OCH * C_];         // concat weights [320][256]
__device__ __align__(16) float g_bias[OCH];           // concat bias
__device__ __align__(16) float g_P[(size_t)B_ * OCH * N_];  // projections [b][320][4096] ~40MB

// ---------------- fp32x2 packed-math helpers (sm_100+ PTX) -----------------
__device__ __forceinline__ unsigned long long pk2(float lo, float hi) {
    unsigned long long r;
    asm("mov.b64 %0, {%1, %2};" : "=l"(r)
        : "r"(__float_as_uint(lo)), "r"(__float_as_uint(hi)));
    return r;
}
__device__ __forceinline__ void upk2(unsigned long long v, float& lo, float& hi) {
    unsigned int a, b;
    asm("mov.b64 {%0, %1}, %2;" : "=r"(a), "=r"(b) : "l"(v));
    lo = __uint_as_float(a); hi = __uint_as_float(b);
}
__device__ __forceinline__ void fma2(unsigned long long& d,
                                     unsigned long long a, unsigned long long b) {
    asm("fma.rn.f32x2 %0, %1, %2, %0;" : "+l"(d) : "l"(a), "l"(b));
}
__device__ __forceinline__ void mul2(unsigned long long& d, unsigned long long a) {
    asm("mul.rn.f32x2 %0, %0, %1;" : "+l"(d) : "l"(a));
}

// ---------------- kernel 0: concatenate wq/wk/wv + biases ------------------
__global__ void concat_kernel(const float* __restrict__ wq, const float* __restrict__ bq,
                              const float* __restrict__ wk, const float* __restrict__ bk,
                              const float* __restrict__ wv, const float* __restrict__ bv) {
    int idx = blockIdx.x * 256 + threadIdx.x;
    if (idx < 32 * C_)            g_W[idx] = wq[idx];
    else if (idx < 64 * C_)       g_W[idx] = wk[idx - 32 * C_];
    else if (idx < OCH * C_)      g_W[idx] = wv[idx - 64 * C_];
    int j = idx - OCH * C_;
    if (j >= 0 && j < OCH) {
        g_bias[j] = (j < 32) ? bq[j] : (j < 64) ? bk[j - 32] : bv[j - 64];
    }
}

// ---------------- kernel 1: projection GEMM P = W @ x + b ------------------
// grid: (N/64 token tiles, B, 320/64 out tiles), 256 threads.
// Each thread computes a 4(out) x 4(token) register tile via fp32x2 FMA.
__global__ void __launch_bounds__(256)
proj_kernel(const float* __restrict__ x) {
    __shared__ __align__(16) float ws[32 * 68];  // [cc][o], padded
    __shared__ __align__(16) float xs[32 * 68];  // [cc][t], padded

    const int tid = threadIdx.x;
    const int n0  = blockIdx.x * 64;
    const int bb  = blockIdx.y;
    const int o0  = blockIdx.z * 64;
    const int tg  = tid & 15;       // token group (16)
    const int og  = tid >> 4;       // out-ch group (16)

    const float* xb = x + (size_t)bb * C_ * N_;

    unsigned long long acc[4][2];   // [uo][token-pair]
    #pragma unroll
    for (int i = 0; i < 4; i++) { acc[i][0] = 0ull; acc[i][1] = 0ull; }

    for (int cb = 0; cb < C_; cb += 32) {
        #pragma unroll
        for (int r = 0; r < 8; r++) {           // 64 o x 32 cc weights
            int idx = tid + r * 256;
            int ol = idx >> 5, cc = idx & 31;
            ws[cc * 68 + ol] = g_W[(o0 + ol) * C_ + cb + cc];
        }
        #pragma unroll
        for (int r = 0; r < 8; r++) {           // 32 cc x 64 t activations
            int idx = tid + r * 256;
            int cc = idx >> 6, t = idx & 63;
            xs[cc * 68 + t] = xb[(size_t)(cb + cc) * N_ + n0 + t];
        }
        __syncthreads();

        #pragma unroll 8
        for (int cc = 0; cc < 32; cc++) {
            float4 w4 = *(const float4*)&ws[cc * 68 + og * 4];
            float4 x4 = *(const float4*)&xs[cc * 68 + tg * 4];
            unsigned long long xa = pk2(x4.x, x4.y);
            unsigned long long xc = pk2(x4.z, x4.w);
            unsigned long long w0 = pk2(w4.x, w4.x);
            unsigned long long w1 = pk2(w4.y, w4.y);
            unsigned long long w2 = pk2(w4.z, w4.z);
            unsigned long long w3 = pk2(w4.w, w4.w);
            fma2(acc[0][0], xa, w0); fma2(acc[0][1], xc, w0);
            fma2(acc[1][0], xa, w1); fma2(acc[1][1], xc, w1);
            fma2(acc[2][0], xa, w2); fma2(acc[2][1], xc, w2);
            fma2(acc[3][0], xa, w3); fma2(acc[3][1], xc, w3);
        }
        __syncthreads();
    }

    float* P = g_P + ((size_t)bb * OCH + o0) * N_ + n0;
    #pragma unroll
    for (int uo = 0; uo < 4; uo++) {
        int o = og * 4 + uo;
        float bias = g_bias[o0 + o];
        float v0, v1, v2, v3;
        upk2(acc[uo][0], v0, v1);
        upk2(acc[uo][1], v2, v3);
        float4 ov = make_float4(v0 + bias, v1 + bias, v2 + bias, v3 + bias);
        *(float4*)&P[(size_t)o * N_ + tg * 4] = ov;
    }
}

// ---------------- kernel 2: flash attention + residual ---------------------
// Queries = g columns (index j), keys = f columns (index i), values = hh columns.
// Softmax over i. grid (N/TQ, B), 256 threads.
// Thread layout for PV: qgrp = tid>>5 (8 groups of 8 q rows), cgrp = tid&31
// (c = cgrp + 32u, u<8). 8x8 fp32x2 accumulator per thread.
#define FLASH_SMEM_FLOATS 25088   // gs 2048 + fs 2048 + hs 16448 + ps 4352 + 192
#define FLASH_SMEM_BYTES  (FLASH_SMEM_FLOATS * 4)

__global__ void __launch_bounds__(256, 2)
flash_kernel(const float* __restrict__ x, const float* __restrict__ gamma,
             float* __restrict__ out) {
    extern __shared__ __align__(16) float sm[];
    float* gs   = sm;                  // [32][64]   queries (d-major)
    float* fs   = gs + 2048;           // [32][64]   keys
    float* hs   = fs + 2048;           // [64][257]  values (i-major, padded)
    float* ps   = hs + 16448;          // [64][68]   scores/probs (i-major, padded)
    float* m_sh = ps + 4352;           // [64]
    float* l_sh = m_sh + 64;           // [64]
    float* sc_sh = l_sh + 64;          // [64]

    const int tid = threadIdx.x;
    const int bb  = blockIdx.y;
    const int j0  = blockIdx.x * TQ;

    const float* Pb   = g_P + (size_t)bb * OCH * N_;
    const float* fptr = Pb;            // rows 0..31
    const float* gptr = Pb + 32 * N_;  // rows 32..63
    const float* hptr = Pb + 64 * N_;  // rows 64..319

    // load query tile gs[d][q]
    #pragma unroll
    for (int r = 0; r < 2; r++) {
        int idx = tid + r * 256;           // 0..511 float4s
        int d = idx >> 4, q4 = idx & 15;
        *(float4*)&gs[d * 64 + q4 * 4] =
            *(const float4*)&gptr[(size_t)d * N_ + j0 + q4 * 4];
    }
    if (tid < 64) { m_sh[tid] = -INFINITY; l_sh[tid] = 0.0f; }

    const int qgrp = tid >> 5;
    const int cgrp = tid & 31;
    const int tqg  = tid & 15;
    const int tkg  = tid >> 4;

    unsigned long long o2[4][8];       // rows (qgrp*8 + 2r2, +1), cols cgrp+32u
    #pragma unroll
    for (int a = 0; a < 4; a++)
        #pragma unroll
        for (int u = 0; u < 8; u++) o2[a][u] = 0ull;

    for (int k0 = 0; k0 < N_; k0 += TK) {
        __syncthreads();  // prev PV done (and first-iter gs/m/l visible)

        // load key tile fs[d][i]
        #pragma unroll
        for (int r = 0; r < 2; r++) {
            int idx = tid + r * 256;
            int d = idx >> 4, i4 = idx & 15;
            *(float4*)&fs[d * 64 + i4 * 4] =
                *(const float4*)&fptr[(size_t)d * N_ + k0 + i4 * 4];
        }
        // load value tile hs[i][c] (transpose on the fly, pad 257)
        #pragma unroll
        for (int r = 0; r < 16; r++) {
            int idx = tid + r * 256;       // 0..4095 float4s
            int c = idx >> 4, i4 = idx & 15;
            float4 v = *(const float4*)&hptr[(size_t)c * N_ + k0 + i4 * 4];
            hs[(i4 * 4 + 0) * 257 + c] = v.x;
            hs[(i4 * 4 + 1) * 257 + c] = v.y;
            hs[(i4 * 4 + 2) * 257 + c] = v.z;
            hs[(i4 * 4 + 3) * 257 + c] = v.w;
        }
        __syncthreads();

        // ---- QK: s[i][q] = sum_d f[d][i] * g[d][q] --------------------------
        unsigned long long s2[2][4];
        #pragma unroll
        for (int a = 0; a < 2; a++)
            #pragma unroll
            for (int v = 0; v < 4; v++) s2[a][v] = 0ull;

        #pragma unroll 8
        for (int d = 0; d < D_; d++) {
            float4 gq = *(const float4*)&gs[d * 64 + tqg * 4];
            float4 fk = *(const float4*)&fs[d * 64 + tkg * 4];
            unsigned long long ga = pk2(gq.x, gq.y);
            unsigned long long gb = pk2(gq.z, gq.w);
            unsigned long long f0 = pk2(fk.x, fk.x);
            unsigned long long f1 = pk2(fk.y, fk.y);
            unsigned long long f2 = pk2(fk.z, fk.z);
            unsigned long long f3 = pk2(fk.w, fk.w);
            fma2(s2[0][0], ga, f0); fma2(s2[1][0], gb, f0);
            fma2(s2[0][1], ga, f1); fma2(s2[1][1], gb, f1);
            fma2(s2[0][2], ga, f2); fma2(s2[1][2], gb, f2);
            fma2(s2[0][3], ga, f3); fma2(s2[1][3], gb, f3);
        }
        #pragma unroll
        for (int v = 0; v < 4; v++) {
            float a0, a1, a2, a3;
            upk2(s2[0][v], a0, a1);
            upk2(s2[1][v], a2, a3);
            int k = tkg * 4 + v, qb = tqg * 4;
            ps[k * 68 + qb + 0] = a0;
            ps[k * 68 + qb + 1] = a1;
            ps[k * 68 + qb + 2] = a2;
            ps[k * 68 + qb + 3] = a3;
        }
        __syncthreads();

        // ---- online softmax over i (one thread per query) -------------------
        if (tid < 64) {
            int q = tid;
            float mo = m_sh[q], mt = mo;
            #pragma unroll 8
            for (int i = 0; i < TK; i++) mt = fmaxf(mt, ps[i * 68 + q]);
            float sc = __expf(mo - mt);          // 0 on first tile (mo = -inf)
            float ls = 0.0f;
            #pragma unroll 8
            for (int i = 0; i < TK; i++) {
                float e = __expf(ps[i * 68 + q] - mt);
                ps[i * 68 + q] = e;
                ls += e;
            }
            l_sh[q] = l_sh[q] * sc + ls;
            m_sh[q] = mt;
            sc_sh[q] = sc;
        }
        __syncthreads();

        // ---- rescale accumulators ------------------------------------------
        {
            unsigned long long scp[4];
            #pragma unroll
            for (int r2 = 0; r2 < 4; r2++)
                scp[r2] = pk2(sc_sh[qgrp * 8 + 2 * r2], sc_sh[qgrp * 8 + 2 * r2 + 1]);
            #pragma unroll
            for (int r2 = 0; r2 < 4; r2++)
                #pragma unroll
                for (int u = 0; u < 8; u++) mul2(o2[r2][u], scp[r2]);
        }

        // ---- PV: o[q][c] += p[i][q] * h[i][c] --------------------------------
        #pragma unroll 2
        for (int i = 0; i < TK; i++) {
            const float* pr = &ps[i * 68 + qgrp * 8];
            float4 p0 = *(const float4*)pr;
            float4 p1 = *(const float4*)(pr + 4);
            unsigned long long pv0 = pk2(p0.x, p0.y);
            unsigned long long pv1 = pk2(p0.z, p0.w);
            unsigned long long pv2 = pk2(p1.x, p1.y);
            unsigned long long pv3 = pk2(p1.z, p1.w);
            const float* hr = &hs[i * 257 + cgrp];
            #pragma unroll
            for (int u = 0; u < 8; u++) {
                float hv = hr[32 * u];
                unsigned long long h2 = pk2(hv, hv);
                fma2(o2[0][u], pv0, h2);
                fma2(o2[1][u], pv1, h2);
                fma2(o2[2][u], pv2, h2);
                fma2(o2[3][u], pv3, h2);
            }
        }
    }
    __syncthreads();   // all PV reads of hs done before reuse as staging

    // ---- epilogue: out[c][j] = gamma * o/l + x, transposed through smem ----
    const float g0 = gamma[0];
    float linv[8];
    #pragma unroll
    for (int r = 0; r < 8; r++) linv[r] = g0 / l_sh[qgrp * 8 + r];

    #pragma unroll
    for (int r2 = 0; r2 < 4; r2++) {
        #pragma unroll
        for (int u = 0; u < 8; u++) {
            float lo, hi;
            upk2(o2[r2][u], lo, hi);
            int c = cgrp + 32 * u;
            hs[(qgrp * 8 + 2 * r2 + 0) * 257 + c] = lo * linv[2 * r2 + 0];
            hs[(qgrp * 8 + 2 * r2 + 1) * 257 + c] = hi * linv[2 * r2 + 1];
        }
    }
    __syncthreads();

    const float* xb = x   + (size_t)bb * C_ * N_;
    float*       ob = out + (size_t)bb * C_ * N_;
    #pragma unroll
    for (int r = 0; r < 16; r++) {
        int idx = tid + r * 256;           // 0..4095 float4s
        int c = idx >> 4, j4 = idx & 15;
        float4 xv = *(const float4*)&xb[(size_t)c * N_ + j0 + j4 * 4];
        float4 ov;
        ov.x = hs[(j4 * 4 + 0) * 257 + c] + xv.x;
        ov.y = hs[(j4 * 4 + 1) * 257 + c] + xv.y;
        ov.z = hs[(j4 * 4 + 2) * 257 + c] + xv.z;
        ov.w = hs[(j4 * 4 + 3) * 257 + c] + xv.w;
        *(float4*)&ob[(size_t)c * N_ + j0 + j4 * 4] = ov;
    }
}

// ---------------- launch ----------------------------------------------------
extern "C" void kernel_launch(void* const* d_in, const int* in_sizes, int n_in,
                              void* d_out, int out_size) {
    (void)in_sizes; (void)n_in; (void)out_size;
    const float* x     = (const float*)d_in[0];
    const float* wq    = (const float*)d_in[1];
    const float* bq    = (const float*)d_in[2];
    const float* wk    = (const float*)d_in[3];
    const float* bk    = (const float*)d_in[4];
    const float* wv    = (const float*)d_in[5];
    const float* bv    = (const float*)d_in[6];
    const float* gamma = (const float*)d_in[7];
    float* out = (float*)d_out;

    cudaFuncSetAttribute(flash_kernel,
                         cudaFuncAttributeMaxDynamicSharedMemorySize,
                         FLASH_SMEM_BYTES);

    concat_kernel<<<322, 256>>>(wq, bq, wk, bk, wv, bv);
    proj_kernel<<<dim3(N_ / 64, B_, OCH / 64), 256>>>(x);
    flash_kernel<<<dim3(N_ / TQ, B_), 256, FLASH_SMEM_BYTES>>>(x, gamma, out);
}